// round 1
// baseline (speedup 1.0000x reference)
#include <cuda_runtime.h>

#define B_SZ   8
#define L_SEQ  4096
#define NDIM   256
#define HDIM   256
#define BL     (B_SZ * L_SEQ)        // 32768
#define CHUNK  128
#define NCHUNK (L_SEQ / CHUNK)       // 32

// ---------------- scratch (device globals; no cudaMalloc allowed) ----------
__device__ float2 g_Bu[(size_t)BL * NDIM];     // 64 MB: Bu, then states (in place)
__device__ float2 g_W[NDIM * HDIM];            // B_norm = (B_re + i B_im) * gamma[n]
__device__ float2 g_Lam[NDIM];                 // Lambda
__device__ float2 g_LamChunk[NDIM];            // Lambda^CHUNK
__device__ float2 g_LamPow[CHUNK * NDIM];      // Lambda^(j+1), j = 0..CHUNK-1
__device__ float2 g_carry[B_SZ * NCHUNK * NDIM];

// ---------------- kernel 0: params + weights -------------------------------
__global__ void prep_kernel(const float* __restrict__ nu_log,
                            const float* __restrict__ theta_log,
                            const float* __restrict__ B_re,
                            const float* __restrict__ B_im) {
    int n = threadIdx.x;                 // 256 threads
    float nu    = expf(nu_log[n]);
    float th    = expf(theta_log[n]);
    float r     = expf(-nu);             // |Lambda|
    float lre   = r * cosf(th);
    float lim   = r * sinf(th);
    float gamma = sqrtf(fmaxf(1.0f - r * r, 0.0f));
    g_Lam[n] = make_float2(lre, lim);

    // powers of Lambda in double (|Lambda| can be ~1 -> long chains matter)
    double pr = 1.0, pi = 0.0;
    double lr = (double)lre, li = (double)lim;
    #pragma unroll 1
    for (int j = 0; j < CHUNK; ++j) {
        double nr = pr * lr - pi * li;
        double ni = pr * li + pi * lr;
        pr = nr; pi = ni;
        g_LamPow[j * NDIM + n] = make_float2((float)pr, (float)pi);  // Lambda^(j+1)
    }
    g_LamChunk[n] = make_float2((float)pr, (float)pi);               // Lambda^CHUNK

    #pragma unroll 1
    for (int h = 0; h < HDIM; ++h) {
        g_W[n * HDIM + h] = make_float2(B_re[n * HDIM + h] * gamma,
                                        B_im[n * HDIM + h] * gamma);
    }
}

// ---------------- GEMM tiling params ----------------------------------------
#define BM 64
#define BN 64
#define BK 16

// ---------------- kernel 1: Bu[bl,n] = sum_h x[bl,h] * W[n,h]  (complex out)
__global__ __launch_bounds__(256) void gemm1_kernel(const float* __restrict__ x) {
    __shared__ float  sA[BK][BM + 1];        // +1 pad: conflict-free STS/LDS
    __shared__ float2 sW[BK][BN + 1];

    const int bm = blockIdx.x * BM;          // over BL rows
    const int bn = blockIdx.y * BN;          // over N cols
    const int t  = threadIdx.x;
    const int tx = t & 15;
    const int ty = t >> 4;

    float2 acc[4][4];
    #pragma unroll
    for (int i = 0; i < 4; ++i)
        #pragma unroll
        for (int j = 0; j < 4; ++j) acc[i][j] = make_float2(0.f, 0.f);

    const int ka = t & (BK - 1);
    const int ra = t >> 4;                   // 0..15

    for (int k0 = 0; k0 < HDIM; k0 += BK) {
        #pragma unroll
        for (int rr = 0; rr < 4; ++rr) {
            int r = ra + rr * 16;
            sA[ka][r] = x[(size_t)(bm + r) * HDIM + k0 + ka];
            sW[ka][r] = g_W[(size_t)(bn + r) * HDIM + k0 + ka];
        }
        __syncthreads();

        #pragma unroll
        for (int k = 0; k < BK; ++k) {
            float  a[4]; float2 w[4];
            #pragma unroll
            for (int i = 0; i < 4; ++i) a[i] = sA[k][ty * 4 + i];
            #pragma unroll
            for (int j = 0; j < 4; ++j) w[j] = sW[k][tx * 4 + j];
            #pragma unroll
            for (int i = 0; i < 4; ++i)
                #pragma unroll
                for (int j = 0; j < 4; ++j) {
                    acc[i][j].x = fmaf(a[i], w[j].x, acc[i][j].x);
                    acc[i][j].y = fmaf(a[i], w[j].y, acc[i][j].y);
                }
        }
        __syncthreads();
    }

    #pragma unroll
    for (int i = 0; i < 4; ++i) {
        const size_t row = bm + ty * 4 + i;
        #pragma unroll
        for (int j = 0; j < 4; ++j)
            g_Bu[row * NDIM + bn + tx * 4 + j] = acc[i][j];
    }
}

// ---------------- kernel 2: local scan within each CHUNK (in place) --------
__global__ __launch_bounds__(256) void scanA_kernel() {
    const int n  = threadIdx.x;
    const int bc = blockIdx.x;               // b*NCHUNK + c
    const float2 lam = g_Lam[n];
    float2 s = make_float2(0.f, 0.f);
    const size_t base = ((size_t)bc * CHUNK) * NDIM + n;

    #pragma unroll 1
    for (int j0 = 0; j0 < CHUNK; j0 += 8) {
        float2 bu[8];
        #pragma unroll
        for (int u = 0; u < 8; ++u)
            bu[u] = g_Bu[base + (size_t)(j0 + u) * NDIM];
        #pragma unroll
        for (int u = 0; u < 8; ++u) {
            float sx = fmaf(lam.x, s.x, fmaf(-lam.y, s.y, bu[u].x));
            float sy = fmaf(lam.x, s.y, fmaf( lam.y, s.x, bu[u].y));
            s.x = sx; s.y = sy;
            g_Bu[base + (size_t)(j0 + u) * NDIM] = s;
        }
    }
    g_carry[(size_t)bc * NDIM + n] = s;      // local end state of chunk
}

// ---------------- kernel 3: sequential scan across chunk carries -----------
__global__ void scanB_kernel() {
    const int n = threadIdx.x;
    const int b = blockIdx.x;                // 8 blocks
    const float2 lc = g_LamChunk[n];
    float2 cin = make_float2(0.f, 0.f);
    #pragma unroll 1
    for (int c = 0; c < NCHUNK; ++c) {
        const size_t idx = ((size_t)b * NCHUNK + c) * NDIM + n;
        float2 e = g_carry[idx];
        g_carry[idx] = cin;                  // carry INTO chunk c
        float nx = fmaf(lc.x, cin.x, fmaf(-lc.y, cin.y, e.x));
        float ny = fmaf(lc.x, cin.y, fmaf( lc.y, cin.x, e.y));
        cin = make_float2(nx, ny);
    }
}

// ---------------- kernel 4: fix-up: state += Lambda^(j+1) * carry_in -------
__global__ __launch_bounds__(256) void scanC_kernel() {
    const size_t idx = (size_t)blockIdx.x * blockDim.x + threadIdx.x;
    const int n  = (int)(idx % NDIM);
    const size_t bl = idx / NDIM;
    const int l  = (int)(bl % L_SEQ);
    const int b  = (int)(bl / L_SEQ);
    const int c  = l / CHUNK;
    const int j  = l % CHUNK;
    const float2 cin = g_carry[((size_t)b * NCHUNK + c) * NDIM + n];
    const float2 p   = g_LamPow[j * NDIM + n];
    float2 v = g_Bu[idx];
    v.x = fmaf(p.x, cin.x, fmaf(-p.y, cin.y, v.x));
    v.y = fmaf(p.x, cin.y, fmaf( p.y, cin.x, v.y));
    g_Bu[idx] = v;
}

// ---------------- kernel 5: y = Re(S @ C^T) + x*D ---------------------------
__global__ __launch_bounds__(256) void gemm2_kernel(const float* __restrict__ Cre,
                                                    const float* __restrict__ Cim,
                                                    const float* __restrict__ x,
                                                    const float* __restrict__ D,
                                                    float* __restrict__ y) {
    __shared__ float2 sS[BK][BM + 1];
    __shared__ float2 sC[BK][BN + 1];

    const int bm = blockIdx.x * BM;
    const int bh = blockIdx.y * BN;
    const int t  = threadIdx.x;
    const int tx = t & 15;
    const int ty = t >> 4;

    float acc[4][4];
    #pragma unroll
    for (int i = 0; i < 4; ++i)
        #pragma unroll
        for (int j = 0; j < 4; ++j) acc[i][j] = 0.f;

    const int ka = t & (BK - 1);
    const int ra = t >> 4;

    for (int k0 = 0; k0 < NDIM; k0 += BK) {
        #pragma unroll
        for (int rr = 0; rr < 4; ++rr) {
            int r = ra + rr * 16;
            sS[ka][r] = g_Bu[(size_t)(bm + r) * NDIM + k0 + ka];
            sC[ka][r] = make_float2(Cre[(size_t)(bh + r) * NDIM + k0 + ka],
                                    Cim[(size_t)(bh + r) * NDIM + k0 + ka]);
        }
        __syncthreads();

        #pragma unroll
        for (int k = 0; k < BK; ++k) {
            float2 s[4]; float2 cc[4];
            #pragma unroll
            for (int i = 0; i < 4; ++i) s[i]  = sS[k][ty * 4 + i];
            #pragma unroll
            for (int j = 0; j < 4; ++j) cc[j] = sC[k][tx * 4 + j];
            #pragma unroll
            for (int i = 0; i < 4; ++i)
                #pragma unroll
                for (int j = 0; j < 4; ++j) {
                    acc[i][j] = fmaf( s[i].x, cc[j].x, acc[i][j]);
                    acc[i][j] = fmaf(-s[i].y, cc[j].y, acc[i][j]);
                }
        }
        __syncthreads();
    }

    #pragma unroll
    for (int i = 0; i < 4; ++i) {
        const size_t row = bm + ty * 4 + i;
        #pragma unroll
        for (int j = 0; j < 4; ++j) {
            const int h = bh + tx * 4 + j;
            y[row * HDIM + h] = acc[i][j] + x[row * HDIM + h] * D[h];
        }
    }
}

// ---------------- launch -----------------------------------------------------
extern "C" void kernel_launch(void* const* d_in, const int* in_sizes, int n_in,
                              void* d_out, int out_size) {
    const float* x         = (const float*)d_in[0];
    const float* B_re      = (const float*)d_in[1];
    const float* B_im      = (const float*)d_in[2];
    const float* C_re      = (const float*)d_in[3];
    const float* C_im      = (const float*)d_in[4];
    const float* nu_log    = (const float*)d_in[5];
    const float* theta_log = (const float*)d_in[6];
    const float* D         = (const float*)d_in[7];
    float* y = (float*)d_out;

    prep_kernel<<<1, 256>>>(nu_log, theta_log, B_re, B_im);
    gemm1_kernel<<<dim3(BL / BM, NDIM / BN), 256>>>(x);
    scanA_kernel<<<B_SZ * NCHUNK, NDIM>>>();
    scanB_kernel<<<B_SZ, NDIM>>>();
    scanC_kernel<<<(BL * NDIM) / 256, 256>>>();
    gemm2_kernel<<<dim3(BL / BM, HDIM / BN), 256>>>(C_re, C_im, x, D, y);
}

// round 2
// speedup vs baseline: 1.7948x; 1.7948x over previous
#include <cuda_runtime.h>
#include <cuda_bf16.h>

#define B_SZ   8
#define L_SEQ  4096
#define NDIM   256
#define HDIM   256
#define BL     (B_SZ * L_SEQ)        // 32768
#define CHUNK  128
#define NCHUNK (L_SEQ / CHUNK)       // 32

// ---------------- scratch (device globals; no cudaMalloc allowed) ----------
__device__ __align__(256) float2        g_Bu[(size_t)BL * NDIM];       // 64 MB (fp32 Bu)
__device__ __align__(256) __nv_bfloat16 g_xhi[(size_t)BL * HDIM];      // 16 MB
__device__ __align__(256) __nv_bfloat16 g_xlo[(size_t)BL * HDIM];
__device__ __align__(256) __nv_bfloat16 g_Shi[(size_t)BL * 2 * NDIM];  // 32 MB (states, re/im interleaved)
__device__ __align__(256) __nv_bfloat16 g_Slo[(size_t)BL * 2 * NDIM];
__device__ __align__(256) __nv_bfloat16 g_W2hi[2 * NDIM * HDIM];       // [512][256]
__device__ __align__(256) __nv_bfloat16 g_W2lo[2 * NDIM * HDIM];
__device__ __align__(256) __nv_bfloat16 g_C2hi[HDIM * 2 * NDIM];       // [256][512]
__device__ __align__(256) __nv_bfloat16 g_C2lo[HDIM * 2 * NDIM];
__device__ float2 g_Lam[NDIM];
__device__ float2 g_LamChunk[NDIM];
__device__ float2 g_carry[B_SZ * NCHUNK * NDIM];

// ---------------- small helpers --------------------------------------------
__device__ __forceinline__ void split_bf16(float v, __nv_bfloat16& h, __nv_bfloat16& l) {
    h = __float2bfloat16_rn(v);
    l = __float2bfloat16_rn(v - __bfloat162float(h));
}

__device__ __forceinline__ void ldm_x4(unsigned* r, unsigned addr) {
    asm volatile("ldmatrix.sync.aligned.m8n8.x4.shared.b16 {%0,%1,%2,%3}, [%4];"
                 : "=r"(r[0]), "=r"(r[1]), "=r"(r[2]), "=r"(r[3]) : "r"(addr));
}

__device__ __forceinline__ void mma_bf16(float* c, const unsigned* a, const unsigned* b) {
    asm volatile("mma.sync.aligned.m16n8k16.row.col.f32.bf16.bf16.f32 "
                 "{%0,%1,%2,%3}, {%4,%5,%6,%7}, {%8,%9}, {%0,%1,%2,%3};"
                 : "+f"(c[0]), "+f"(c[1]), "+f"(c[2]), "+f"(c[3])
                 : "r"(a[0]), "r"(a[1]), "r"(a[2]), "r"(a[3]), "r"(b[0]), "r"(b[1]));
}

__device__ __forceinline__ void cp16(unsigned dst, const void* src) {
    asm volatile("cp.async.cg.shared.global [%0], [%1], 16;" :: "r"(dst), "l"(src));
}

// ---------------- kernel 0a: params + weight splits -------------------------
__global__ void prep_params_kernel(const float* __restrict__ nu_log,
                                   const float* __restrict__ theta_log,
                                   const float* __restrict__ B_re,
                                   const float* __restrict__ B_im,
                                   const float* __restrict__ C_re,
                                   const float* __restrict__ C_im) {
    int n = threadIdx.x;  // 256 threads
    float nu    = expf(nu_log[n]);
    float th    = expf(theta_log[n]);
    float r     = expf(-nu);
    float lre   = r * cosf(th);
    float lim   = r * sinf(th);
    float gamma = sqrtf(fmaxf(1.0f - r * r, 0.0f));
    g_Lam[n] = make_float2(lre, lim);

    double pr = 1.0, pi = 0.0, lr = lre, li = lim;
    #pragma unroll 1
    for (int j = 0; j < CHUNK; ++j) {
        double nr = pr * lr - pi * li;
        double ni = pr * li + pi * lr;
        pr = nr; pi = ni;
    }
    g_LamChunk[n] = make_float2((float)pr, (float)pi);

    // W2: row 2n = gamma*B_re[n,:], row 2n+1 = gamma*B_im[n,:]
    #pragma unroll 1
    for (int h = 0; h < HDIM; ++h) {
        __nv_bfloat16 hh, ll;
        split_bf16(B_re[n * HDIM + h] * gamma, hh, ll);
        g_W2hi[(2 * n) * HDIM + h] = hh;  g_W2lo[(2 * n) * HDIM + h] = ll;
        split_bf16(B_im[n * HDIM + h] * gamma, hh, ll);
        g_W2hi[(2 * n + 1) * HDIM + h] = hh;  g_W2lo[(2 * n + 1) * HDIM + h] = ll;
    }
    // C2: row h, col 2k = C_re[h,k], col 2k+1 = -C_im[h,k]  (thread n handles row h=n)
    int h = n;
    #pragma unroll 1
    for (int k = 0; k < NDIM; ++k) {
        __nv_bfloat16 hh, ll;
        split_bf16(C_re[h * NDIM + k], hh, ll);
        g_C2hi[h * 512 + 2 * k] = hh;  g_C2lo[h * 512 + 2 * k] = ll;
        split_bf16(-C_im[h * NDIM + k], hh, ll);
        g_C2hi[h * 512 + 2 * k + 1] = hh;  g_C2lo[h * 512 + 2 * k + 1] = ll;
    }
}

// ---------------- kernel 0b: split x into bf16 hi/lo -------------------------
__global__ __launch_bounds__(256) void prep_x_kernel(const float* __restrict__ x) {
    size_t i = ((size_t)blockIdx.x * 256 + threadIdx.x) * 4;
    float4 v = *(const float4*)(x + i);
    __nv_bfloat16 h0, l0, h1, l1, h2, l2, h3, l3;
    split_bf16(v.x, h0, l0); split_bf16(v.y, h1, l1);
    split_bf16(v.z, h2, l2); split_bf16(v.w, h3, l3);
    *(__nv_bfloat162*)(g_xhi + i)     = __nv_bfloat162(h0, h1);
    *(__nv_bfloat162*)(g_xhi + i + 2) = __nv_bfloat162(h2, h3);
    *(__nv_bfloat162*)(g_xlo + i)     = __nv_bfloat162(l0, l1);
    *(__nv_bfloat162*)(g_xlo + i + 2) = __nv_bfloat162(l2, l3);
}

// ---------------- split-bf16 tensor-core GEMM -------------------------------
// C[M,N] = A[M,K] * B[N,K]^T,  A/B given as bf16 hi/lo split, fp32 accumulate.
#define BMT 128
#define BNT 64
#define BKT 32
#define SSTG ((BMT + BNT) * BKT)   // bf16 elems per (stage,split) = 6144

template<int K, int N, bool EPI>
__device__ __forceinline__ void gemm_body(
    const __nv_bfloat16* __restrict__ Ahi, const __nv_bfloat16* __restrict__ Alo,
    const __nv_bfloat16* __restrict__ Bhi, const __nv_bfloat16* __restrict__ Blo,
    float* __restrict__ out,
    const float* __restrict__ xres, const float* __restrict__ Dres)
{
    __shared__ __align__(16) __nv_bfloat16 smem[4 * SSTG];  // [stage][split] = 48KB

    const int t = threadIdx.x;
    const int lane = t & 31, warp = t >> 5;
    const int warp_m = warp >> 1, warp_n = warp & 1;
    const int bm = blockIdx.x * BMT, bn = blockIdx.y * BNT;

    const unsigned sbase = (unsigned)__cvta_generic_to_shared(smem);

    float acc[2][4][4];
    #pragma unroll
    for (int i = 0; i < 2; ++i)
        #pragma unroll
        for (int j = 0; j < 4; ++j)
            #pragma unroll
            for (int q = 0; q < 4; ++q) acc[i][j][q] = 0.f;

    // precomputed per-thread cp.async slots
    const int arow0 = t >> 2,        ac = t & 3;
    const int arow1 = (t + 256) >> 2;
    const int brow  = t >> 2,        bc = t & 3;
    const int asc0 = ac ^ ((arow0 >> 1) & 3);
    const int asc1 = ac ^ ((arow1 >> 1) & 3);
    const int bsc  = bc ^ ((brow >> 1) & 3);

    constexpr int KT = K / BKT;

    // ---- stage loader ----
    auto load_stage = [&](int kt, int stage) {
        const int k0 = kt * BKT;
        #pragma unroll
        for (int sp = 0; sp < 2; ++sp) {
            const __nv_bfloat16* A = sp ? Alo : Ahi;
            const __nv_bfloat16* B = sp ? Blo : Bhi;
            const unsigned base = sbase + (unsigned)((stage * 2 + sp) * SSTG) * 2u;
            cp16(base + (arow0 * BKT + asc0 * 8) * 2,
                 A + (size_t)(bm + arow0) * K + k0 + ac * 8);
            cp16(base + (arow1 * BKT + asc1 * 8) * 2,
                 A + (size_t)(bm + arow1) * K + k0 + ac * 8);
            cp16(base + (unsigned)(BMT * BKT) * 2 + (brow * BKT + bsc * 8) * 2,
                 B + (size_t)(bn + brow) * K + k0 + bc * 8);
        }
    };

    load_stage(0, 0);
    asm volatile("cp.async.commit_group;");

    #pragma unroll 1
    for (int kt = 0; kt < KT; ++kt) {
        if (kt + 1 < KT) load_stage(kt + 1, (kt + 1) & 1);
        asm volatile("cp.async.commit_group;");
        asm volatile("cp.async.wait_group 1;");
        __syncthreads();

        const int stage = kt & 1;
        const unsigned baseA0 = sbase + (unsigned)((stage * 2 + 0) * SSTG) * 2u;
        const unsigned baseA1 = sbase + (unsigned)((stage * 2 + 1) * SSTG) * 2u;
        const unsigned baseB0 = baseA0 + (unsigned)(BMT * BKT) * 2u;
        const unsigned baseB1 = baseA1 + (unsigned)(BMT * BKT) * 2u;

        #pragma unroll
        for (int kk = 0; kk < BKT; kk += 16) {
            unsigned a[2][2][4], b[2][2][4];
            #pragma unroll
            for (int mt = 0; mt < 2; ++mt) {
                int r  = warp_m * 32 + mt * 16 + (lane & 15);
                int kc = (kk >> 3) + (lane >> 4);
                int sc = kc ^ ((r >> 1) & 3);
                unsigned off = (unsigned)(r * BKT + sc * 8) * 2u;
                ldm_x4(a[mt][0], baseA0 + off);
                ldm_x4(a[mt][1], baseA1 + off);
            }
            #pragma unroll
            for (int p = 0; p < 2; ++p) {
                int r  = warp_n * 32 + p * 16 + (lane & 7) + ((lane >> 4) << 3);
                int kc = (kk >> 3) + ((lane >> 3) & 1);
                int sc = kc ^ ((r >> 1) & 3);
                unsigned off = (unsigned)(r * BKT + sc * 8) * 2u;
                ldm_x4(b[p][0], baseB0 + off);
                ldm_x4(b[p][1], baseB1 + off);
            }
            #pragma unroll
            for (int mt = 0; mt < 2; ++mt)
                #pragma unroll
                for (int nt = 0; nt < 4; ++nt) {
                    const int p = nt >> 1, sub = (nt & 1) * 2;
                    mma_bf16(acc[mt][nt], a[mt][0], &b[p][0][sub]);  // hi*hi
                    mma_bf16(acc[mt][nt], a[mt][0], &b[p][1][sub]);  // hi*lo
                    mma_bf16(acc[mt][nt], a[mt][1], &b[p][0][sub]);  // lo*hi
                }
        }
        __syncthreads();
    }

    // ---- epilogue ----
    #pragma unroll
    for (int mt = 0; mt < 2; ++mt)
        #pragma unroll
        for (int nt = 0; nt < 4; ++nt) {
            const int row = bm + warp_m * 32 + mt * 16 + (lane >> 2);
            const int col = bn + warp_n * 32 + nt * 8 + (lane & 3) * 2;
            const float* c = acc[mt][nt];
            if (!EPI) {
                *(float2*)(out + (size_t)row * N + col)       = make_float2(c[0], c[1]);
                *(float2*)(out + (size_t)(row + 8) * N + col) = make_float2(c[2], c[3]);
            } else {
                float2 d  = *(const float2*)(Dres + col);
                float2 x0 = *(const float2*)(xres + (size_t)row * N + col);
                float2 x1 = *(const float2*)(xres + (size_t)(row + 8) * N + col);
                *(float2*)(out + (size_t)row * N + col) =
                    make_float2(c[0] + x0.x * d.x, c[1] + x0.y * d.y);
                *(float2*)(out + (size_t)(row + 8) * N + col) =
                    make_float2(c[2] + x1.x * d.x, c[3] + x1.y * d.y);
            }
        }
}

__global__ __launch_bounds__(256, 2) void gemm1_mma_kernel() {
    gemm_body<HDIM, 2 * NDIM, false>(g_xhi, g_xlo, g_W2hi, g_W2lo,
                                     (float*)g_Bu, nullptr, nullptr);
}

__global__ __launch_bounds__(256, 2) void gemm2_mma_kernel(const float* __restrict__ x,
                                                           const float* __restrict__ D,
                                                           float* __restrict__ y) {
    gemm_body<2 * NDIM, HDIM, true>(g_Shi, g_Slo, g_C2hi, g_C2lo, y, x, D);
}

// ---------------- kernel 2: chunk-end carries only --------------------------
__global__ __launch_bounds__(256) void scanA_kernel() {
    const int n  = threadIdx.x;
    const int bc = blockIdx.x;
    const float2 lam = g_Lam[n];
    float2 s = make_float2(0.f, 0.f);
    const float2* p = g_Bu + (size_t)bc * CHUNK * NDIM + n;

    #pragma unroll 1
    for (int j0 = 0; j0 < CHUNK; j0 += 8) {
        float2 bu[8];
        #pragma unroll
        for (int u = 0; u < 8; ++u) bu[u] = p[(size_t)(j0 + u) * NDIM];
        #pragma unroll
        for (int u = 0; u < 8; ++u) {
            float sx = fmaf(lam.x, s.x, fmaf(-lam.y, s.y, bu[u].x));
            float sy = fmaf(lam.x, s.y, fmaf( lam.y, s.x, bu[u].y));
            s.x = sx; s.y = sy;
        }
    }
    g_carry[(size_t)bc * NDIM + n] = s;
}

// ---------------- kernel 3: cross-chunk carry scan (registers) --------------
__global__ void scanB_kernel() {
    const int n = threadIdx.x;
    const int b = blockIdx.x;
    const float2 lc = g_LamChunk[n];
    float2 e[NCHUNK];
    #pragma unroll
    for (int c = 0; c < NCHUNK; ++c)
        e[c] = g_carry[((size_t)b * NCHUNK + c) * NDIM + n];
    float2 cin = make_float2(0.f, 0.f);
    #pragma unroll
    for (int c = 0; c < NCHUNK; ++c) {
        float2 old = e[c];
        g_carry[((size_t)b * NCHUNK + c) * NDIM + n] = cin;  // carry INTO chunk c
        float nx = fmaf(lc.x, cin.x, fmaf(-lc.y, cin.y, old.x));
        float ny = fmaf(lc.x, cin.y, fmaf( lc.y, cin.x, old.y));
        cin = make_float2(nx, ny);
    }
}

// ---------------- kernel 4: rescan with carry-in, emit bf16 hi/lo states ---
__global__ __launch_bounds__(256) void scanC_kernel() {
    const int n  = threadIdx.x;
    const int bc = blockIdx.x;
    const float2 lam = g_Lam[n];
    float2 s = g_carry[(size_t)bc * NDIM + n];
    const float2* p = g_Bu + (size_t)bc * CHUNK * NDIM + n;
    __nv_bfloat162* outh = (__nv_bfloat162*)g_Shi + (size_t)bc * CHUNK * NDIM + n;
    __nv_bfloat162* outl = (__nv_bfloat162*)g_Slo + (size_t)bc * CHUNK * NDIM + n;

    #pragma unroll 1
    for (int j0 = 0; j0 < CHUNK; j0 += 8) {
        float2 bu[8];
        #pragma unroll
        for (int u = 0; u < 8; ++u) bu[u] = p[(size_t)(j0 + u) * NDIM];
        #pragma unroll
        for (int u = 0; u < 8; ++u) {
            float sx = fmaf(lam.x, s.x, fmaf(-lam.y, s.y, bu[u].x));
            float sy = fmaf(lam.x, s.y, fmaf( lam.y, s.x, bu[u].y));
            s.x = sx; s.y = sy;
            __nv_bfloat16 hx, lx, hy, ly;
            split_bf16(s.x, hx, lx);
            split_bf16(s.y, hy, ly);
            outh[(size_t)(j0 + u) * NDIM] = __nv_bfloat162(hx, hy);
            outl[(size_t)(j0 + u) * NDIM] = __nv_bfloat162(lx, ly);
        }
    }
}

// ---------------- launch -----------------------------------------------------
extern "C" void kernel_launch(void* const* d_in, const int* in_sizes, int n_in,
                              void* d_out, int out_size) {
    const float* x         = (const float*)d_in[0];
    const float* B_re      = (const float*)d_in[1];
    const float* B_im      = (const float*)d_in[2];
    const float* C_re      = (const float*)d_in[3];
    const float* C_im      = (const float*)d_in[4];
    const float* nu_log    = (const float*)d_in[5];
    const float* theta_log = (const float*)d_in[6];
    const float* D         = (const float*)d_in[7];
    float* y = (float*)d_out;

    prep_params_kernel<<<1, 256>>>(nu_log, theta_log, B_re, B_im, C_re, C_im);
    prep_x_kernel<<<(BL * HDIM) / 1024, 256>>>(x);
    gemm1_mma_kernel<<<dim3(BL / BMT, (2 * NDIM) / BNT), 256>>>();
    scanA_kernel<<<B_SZ * NCHUNK, NDIM>>>();
    scanB_kernel<<<B_SZ, NDIM>>>();
    scanC_kernel<<<B_SZ * NCHUNK, NDIM>>>();
    gemm2_mma_kernel<<<dim3(BL / BMT, HDIM / BNT), 256>>>(x, D, y);
}

// round 4
// speedup vs baseline: 5.1816x; 2.8870x over previous
#include <cuda_runtime.h>
#include <cuda_bf16.h>
#include <cstdint>

#define B_SZ   8
#define L_SEQ  4096
#define NDIM   256
#define HDIM   256
#define BL     (B_SZ * L_SEQ)        // 32768
#define CHUNK  128
#define NCHUNK (L_SEQ / CHUNK)       // 32

// ---------------- scratch (device globals; no cudaMalloc allowed) ----------
__device__ __align__(256) float2        g_Bu[(size_t)BL * NDIM];       // 64 MB
__device__ __align__(256) __nv_bfloat16 g_xhi[(size_t)BL * HDIM];      // 16 MB
__device__ __align__(256) __nv_bfloat16 g_xlo[(size_t)BL * HDIM];
__device__ __align__(256) __nv_bfloat16 g_Shi[(size_t)BL * 2 * NDIM];  // 32 MB
__device__ __align__(256) __nv_bfloat16 g_Slo[(size_t)BL * 2 * NDIM];
__device__ __align__(256) __nv_bfloat16 g_W2hi[2 * NDIM * HDIM];       // [512][256]
__device__ __align__(256) __nv_bfloat16 g_W2lo[2 * NDIM * HDIM];
__device__ __align__(256) __nv_bfloat16 g_C2hi[HDIM * 2 * NDIM];       // [256][512]
__device__ __align__(256) __nv_bfloat16 g_C2lo[HDIM * 2 * NDIM];
__device__ float2 g_Lam[NDIM];
__device__ float2 g_LamChunk[NDIM];
__device__ float2 g_carry[B_SZ * NCHUNK * NDIM];

// ---------------- helpers ----------------------------------------------------
__device__ __forceinline__ void split_bf16(float v, __nv_bfloat16& h, __nv_bfloat16& l) {
    h = __float2bfloat16_rn(v);
    l = __float2bfloat16_rn(v - __bfloat162float(h));
}

__device__ __forceinline__ void cp16(unsigned dst, const void* src) {
    asm volatile("cp.async.cg.shared.global [%0], [%1], 16;" :: "r"(dst), "l"(src));
}

__device__ __forceinline__ void ldm_x4(unsigned* r, unsigned addr) {
    asm volatile("ldmatrix.sync.aligned.m8n8.x4.shared.b16 {%0,%1,%2,%3}, [%4];"
                 : "=r"(r[0]), "=r"(r[1]), "=r"(r[2]), "=r"(r[3]) : "r"(addr));
}

__device__ __forceinline__ void mma_bf16(float* c, const unsigned* a, const unsigned* b) {
    asm volatile("mma.sync.aligned.m16n8k16.row.col.f32.bf16.bf16.f32 "
                 "{%0,%1,%2,%3}, {%4,%5,%6,%7}, {%8,%9}, {%0,%1,%2,%3};"
                 : "+f"(c[0]), "+f"(c[1]), "+f"(c[2]), "+f"(c[3])
                 : "r"(a[0]), "r"(a[1]), "r"(a[2]), "r"(a[3]), "r"(b[0]), "r"(b[1]));
}

#define CP_COMMIT() asm volatile("cp.async.commit_group;" ::: "memory")
#define CP_WAIT2()  asm volatile("cp.async.wait_group 2;" ::: "memory")

// ---------------- prep kernels -----------------------------------------------
__global__ void prep_lam_kernel(const float* __restrict__ nu_log,
                                const float* __restrict__ theta_log) {
    int n = threadIdx.x;
    float nu  = expf(nu_log[n]);
    float th  = expf(theta_log[n]);
    float r   = expf(-nu);
    float lre = r * cosf(th);
    float lim = r * sinf(th);
    g_Lam[n] = make_float2(lre, lim);
    double pr = 1.0, pi = 0.0, lr = lre, li = lim;
    #pragma unroll 1
    for (int j = 0; j < CHUNK; ++j) {
        double nr = pr * lr - pi * li;
        double ni = pr * li + pi * lr;
        pr = nr; pi = ni;
    }
    g_LamChunk[n] = make_float2((float)pr, (float)pi);
}

__global__ void prep_w_kernel(const float* __restrict__ nu_log,
                              const float* __restrict__ B_re,
                              const float* __restrict__ B_im) {
    int n = blockIdx.x, h = threadIdx.x;
    float r = expf(-expf(nu_log[n]));
    float gamma = sqrtf(fmaxf(1.0f - r * r, 0.0f));
    __nv_bfloat16 hh, ll;
    split_bf16(B_re[n * HDIM + h] * gamma, hh, ll);
    g_W2hi[(2 * n) * HDIM + h] = hh;  g_W2lo[(2 * n) * HDIM + h] = ll;
    split_bf16(B_im[n * HDIM + h] * gamma, hh, ll);
    g_W2hi[(2 * n + 1) * HDIM + h] = hh;  g_W2lo[(2 * n + 1) * HDIM + h] = ll;
}

__global__ void prep_c_kernel(const float* __restrict__ C_re,
                              const float* __restrict__ C_im) {
    int h = blockIdx.x, k = threadIdx.x;
    __nv_bfloat16 hre, lre, him, lim;
    split_bf16(C_re[h * NDIM + k], hre, lre);
    split_bf16(-C_im[h * NDIM + k], him, lim);
    *(__nv_bfloat162*)(g_C2hi + h * 512 + 2 * k) = __nv_bfloat162(hre, him);
    *(__nv_bfloat162*)(g_C2lo + h * 512 + 2 * k) = __nv_bfloat162(lre, lim);
}

__global__ __launch_bounds__(256) void prep_x_kernel(const float* __restrict__ x) {
    size_t i = ((size_t)blockIdx.x * 256 + threadIdx.x) * 4;
    float4 v = *(const float4*)(x + i);
    __nv_bfloat16 h0, l0, h1, l1, h2, l2, h3, l3;
    split_bf16(v.x, h0, l0); split_bf16(v.y, h1, l1);
    split_bf16(v.z, h2, l2); split_bf16(v.w, h3, l3);
    *(__nv_bfloat162*)(g_xhi + i)     = __nv_bfloat162(h0, h1);
    *(__nv_bfloat162*)(g_xhi + i + 2) = __nv_bfloat162(h2, h3);
    *(__nv_bfloat162*)(g_xlo + i)     = __nv_bfloat162(l0, l1);
    *(__nv_bfloat162*)(g_xlo + i + 2) = __nv_bfloat162(l2, l3);
}

// ---------------- virtual-K split-bf16 mma.sync GEMM -------------------------
// out[M, NOUT] = Ahi*Bhi^T + Alo*Bhi^T + Ahi*Blo^T   (A:[M][K], B:[NOUT][K])
// CTA tile 128x64, warp tile 32x32 (8 warps), BK=64, 4-stage cp.async.
#define GSTAGES 4
#define GBK     64
#define A_STG_BYTES (128 * 128)        // 128 rows x 128B
#define B_STG_BYTES (64 * 128)
#define SLOT_BYTES  (A_STG_BYTES + B_STG_BYTES)   // 24576
#define G_SMEM_BYTES (GSTAGES * SLOT_BYTES)       // 98304

template<int K, int NOUT, bool EPI>
__device__ __forceinline__ void tc_gemm(
    const __nv_bfloat16* __restrict__ Ahi, const __nv_bfloat16* __restrict__ Alo,
    const __nv_bfloat16* __restrict__ Bhi, const __nv_bfloat16* __restrict__ Blo,
    float* __restrict__ out,
    const float* __restrict__ xres, const float* __restrict__ Dres)
{
    extern __shared__ __align__(1024) char smem[];
    const unsigned sbase = (unsigned)__cvta_generic_to_shared(smem);

    const int t = threadIdx.x, lane = t & 31, warp = t >> 5;
    const int wm = warp >> 1, wn = warp & 1;          // 4 x 2 warps
    const int bm = blockIdx.x * 128, bn = blockIdx.y * 64;

    constexpr int SEG = K / GBK;        // chunks per segment
    constexpr int NCH = 3 * SEG;        // virtual chunks

    const __nv_bfloat16* Aseg[3] = { Ahi, Alo, Ahi };
    const __nv_bfloat16* Bseg[3] = { Bhi, Bhi, Blo };

    float acc[2][4][4];
    #pragma unroll
    for (int i = 0; i < 2; ++i)
        #pragma unroll
        for (int j = 0; j < 4; ++j)
            #pragma unroll
            for (int q = 0; q < 4; ++q) acc[i][j][q] = 0.f;

    // ---- loader: thread t covers 4 A granules + 2 B granules per stage ----
    auto load_chunk = [&](int c) {
        const int slot = c & (GSTAGES - 1);
        const int seg  = c / SEG;
        const int kk0  = (c % SEG) * GBK;
        const __nv_bfloat16* A = Aseg[seg];
        const __nv_bfloat16* B = Bseg[seg];
        const unsigned abase = sbase + slot * SLOT_BYTES;
        const unsigned bbase = abase + A_STG_BYTES;
        #pragma unroll
        for (int i = 0; i < 4; ++i) {
            int idx = t + i * 256;              // 0..1023
            int r = idx >> 3, g = idx & 7;
            cp16(abase + (unsigned)(r * 128 + ((g ^ (r & 7)) << 4)),
                 A + (size_t)(bm + r) * K + kk0 + g * 8);
        }
        #pragma unroll
        for (int i = 0; i < 2; ++i) {
            int idx = t + i * 256;              // 0..511
            int r = idx >> 3, g = idx & 7;
            cp16(bbase + (unsigned)(r * 128 + ((g ^ (r & 7)) << 4)),
                 B + (size_t)(bn + r) * K + kk0 + g * 8);
        }
    };

    // prologue: stages 0..2
    load_chunk(0); CP_COMMIT();
    load_chunk(1); CP_COMMIT();
    load_chunk(2); CP_COMMIT();

    // per-thread fragment address components
    const int ar0 = wm * 32 + (lane & 15);            // a tile 0 row
    const int ar1 = ar0 + 16;                         // a tile 1 row
    const int akc = lane >> 4;                        // granule sub-index
    const int br0 = wn * 32 + (lane & 7) + ((lane >> 4) << 3);
    const int br1 = br0 + 16;
    const int bkc = (lane >> 3) & 1;

    #pragma unroll 1
    for (int c = 0; c < NCH; ++c) {
        CP_WAIT2();
        __syncthreads();

        if (c + 3 < NCH) load_chunk(c + 3);
        CP_COMMIT();

        const int slot = c & (GSTAGES - 1);
        const unsigned abase = sbase + slot * SLOT_BYTES;
        const unsigned bbase = abase + A_STG_BYTES;

        #pragma unroll
        for (int kk = 0; kk < GBK; kk += 16) {
            unsigned a[2][4], b[2][4];
            {
                int kc = (kk >> 3) + akc;
                ldm_x4(a[0], abase + (unsigned)(ar0 * 128 + ((kc ^ (ar0 & 7)) << 4)));
                ldm_x4(a[1], abase + (unsigned)(ar1 * 128 + ((kc ^ (ar1 & 7)) << 4)));
            }
            {
                int kc = (kk >> 3) + bkc;
                ldm_x4(b[0], bbase + (unsigned)(br0 * 128 + ((kc ^ (br0 & 7)) << 4)));
                ldm_x4(b[1], bbase + (unsigned)(br1 * 128 + ((kc ^ (br1 & 7)) << 4)));
            }
            #pragma unroll
            for (int mt = 0; mt < 2; ++mt)
                #pragma unroll
                for (int nt = 0; nt < 4; ++nt)
                    mma_bf16(acc[mt][nt], a[mt], &b[nt >> 1][(nt & 1) * 2]);
        }
        __syncthreads();
    }

    // ---- epilogue ----
    #pragma unroll
    for (int mt = 0; mt < 2; ++mt)
        #pragma unroll
        for (int nt = 0; nt < 4; ++nt) {
            const int row = bm + wm * 32 + mt * 16 + (lane >> 2);
            const int col = bn + wn * 32 + nt * 8 + (lane & 3) * 2;
            const float* c = acc[mt][nt];
            if (!EPI) {
                *(float2*)(out + (size_t)row * NOUT + col)       = make_float2(c[0], c[1]);
                *(float2*)(out + (size_t)(row + 8) * NOUT + col) = make_float2(c[2], c[3]);
            } else {
                float2 d  = *(const float2*)(Dres + col);
                float2 x0 = *(const float2*)(xres + (size_t)row * NOUT + col);
                float2 x1 = *(const float2*)(xres + (size_t)(row + 8) * NOUT + col);
                *(float2*)(out + (size_t)row * NOUT + col) =
                    make_float2(c[0] + x0.x * d.x, c[1] + x0.y * d.y);
                *(float2*)(out + (size_t)(row + 8) * NOUT + col) =
                    make_float2(c[2] + x1.x * d.x, c[3] + x1.y * d.y);
            }
        }
}

__global__ __launch_bounds__(256, 2) void gemm1_kernel() {
    tc_gemm<HDIM, 2 * NDIM, false>(g_xhi, g_xlo, g_W2hi, g_W2lo,
                                   (float*)g_Bu, nullptr, nullptr);
}

__global__ __launch_bounds__(256, 2) void gemm2_kernel(const float* __restrict__ x,
                                                       const float* __restrict__ D,
                                                       float* __restrict__ y) {
    tc_gemm<2 * NDIM, HDIM, true>(g_Shi, g_Slo, g_C2hi, g_C2lo, y, x, D);
}

// ---------------- kernel 2: chunk-end carries only --------------------------
__global__ __launch_bounds__(256) void scanA_kernel() {
    const int n  = threadIdx.x;
    const int bc = blockIdx.x;
    const float2 lam = g_Lam[n];
    float2 s = make_float2(0.f, 0.f);
    const float2* p = g_Bu + (size_t)bc * CHUNK * NDIM + n;

    #pragma unroll 1
    for (int j0 = 0; j0 < CHUNK; j0 += 8) {
        float2 bu[8];
        #pragma unroll
        for (int u = 0; u < 8; ++u) bu[u] = p[(size_t)(j0 + u) * NDIM];
        #pragma unroll
        for (int u = 0; u < 8; ++u) {
            float sx = fmaf(lam.x, s.x, fmaf(-lam.y, s.y, bu[u].x));
            float sy = fmaf(lam.x, s.y, fmaf( lam.y, s.x, bu[u].y));
            s.x = sx; s.y = sy;
        }
    }
    g_carry[(size_t)bc * NDIM + n] = s;
}

// ---------------- kernel 3: cross-chunk carry scan (registers) --------------
__global__ void scanB_kernel() {
    const int n = threadIdx.x;
    const int b = blockIdx.x;
    const float2 lc = g_LamChunk[n];
    float2 e[NCHUNK];
    #pragma unroll
    for (int c = 0; c < NCHUNK; ++c)
        e[c] = g_carry[((size_t)b * NCHUNK + c) * NDIM + n];
    float2 cin = make_float2(0.f, 0.f);
    #pragma unroll
    for (int c = 0; c < NCHUNK; ++c) {
        float2 old = e[c];
        g_carry[((size_t)b * NCHUNK + c) * NDIM + n] = cin;
        float nx = fmaf(lc.x, cin.x, fmaf(-lc.y, cin.y, old.x));
        float ny = fmaf(lc.x, cin.y, fmaf( lc.y, cin.x, old.y));
        cin = make_float2(nx, ny);
    }
}

// ---------------- kernel 4: rescan with carry-in, emit bf16 hi/lo states ---
__global__ __launch_bounds__(256) void scanC_kernel() {
    const int n  = threadIdx.x;
    const int bc = blockIdx.x;
    const float2 lam = g_Lam[n];
    float2 s = g_carry[(size_t)bc * NDIM + n];
    const float2* p = g_Bu + (size_t)bc * CHUNK * NDIM + n;
    __nv_bfloat162* outh = (__nv_bfloat162*)g_Shi + (size_t)bc * CHUNK * NDIM + n;
    __nv_bfloat162* outl = (__nv_bfloat162*)g_Slo + (size_t)bc * CHUNK * NDIM + n;

    #pragma unroll 1
    for (int j0 = 0; j0 < CHUNK; j0 += 8) {
        float2 bu[8];
        #pragma unroll
        for (int u = 0; u < 8; ++u) bu[u] = p[(size_t)(j0 + u) * NDIM];
        #pragma unroll
        for (int u = 0; u < 8; ++u) {
            float sx = fmaf(lam.x, s.x, fmaf(-lam.y, s.y, bu[u].x));
            float sy = fmaf(lam.x, s.y, fmaf( lam.y, s.x, bu[u].y));
            s.x = sx; s.y = sy;
            __nv_bfloat16 hx, lx, hy, ly;
            split_bf16(s.x, hx, lx);
            split_bf16(s.y, hy, ly);
            outh[(size_t)(j0 + u) * NDIM] = __nv_bfloat162(hx, hy);
            outl[(size_t)(j0 + u) * NDIM] = __nv_bfloat162(lx, ly);
        }
    }
}

// ---------------- launch -----------------------------------------------------
extern "C" void kernel_launch(void* const* d_in, const int* in_sizes, int n_in,
                              void* d_out, int out_size) {
    const float* x         = (const float*)d_in[0];
    const float* B_re      = (const float*)d_in[1];
    const float* B_im      = (const float*)d_in[2];
    const float* C_re      = (const float*)d_in[3];
    const float* C_im      = (const float*)d_in[4];
    const float* nu_log    = (const float*)d_in[5];
    const float* theta_log = (const float*)d_in[6];
    const float* D         = (const float*)d_in[7];
    float* y = (float*)d_out;

    cudaFuncSetAttribute(gemm1_kernel,
                         cudaFuncAttributeMaxDynamicSharedMemorySize, G_SMEM_BYTES);
    cudaFuncSetAttribute(gemm2_kernel,
                         cudaFuncAttributeMaxDynamicSharedMemorySize, G_SMEM_BYTES);

    prep_lam_kernel<<<1, 256>>>(nu_log, theta_log);
    prep_w_kernel<<<NDIM, 256>>>(nu_log, B_re, B_im);
    prep_c_kernel<<<HDIM, 256>>>(C_re, C_im);
    prep_x_kernel<<<(BL * HDIM) / 1024, 256>>>(x);
    gemm1_kernel<<<dim3(BL / 128, (2 * NDIM) / 64), 256, G_SMEM_BYTES>>>();
    scanA_kernel<<<B_SZ * NCHUNK, NDIM>>>();
    scanB_kernel<<<B_SZ, NDIM>>>();
    scanC_kernel<<<B_SZ * NCHUNK, NDIM>>>();
    gemm2_kernel<<<dim3(BL / 128, HDIM / 64), 256, G_SMEM_BYTES>>>(x, D, y);
}